// round 2
// baseline (speedup 1.0000x reference)
#include <cuda_runtime.h>
#include <math.h>

// Problem constants (fixed per reference)
#define DN     128      // feature dim
#define HN     256      // hidden dim
#define NNODE  40000
#define NEDGE  640000
#define TM     64       // row tile
#define A2S    260      // A2 smem row stride (floats)
#define YSS    132      // Ys smem row stride (floats)

// Scratch (device globals: no allocation allowed)
__device__ float g_agg[NNODE * DN];
__device__ float g_cnt[NNODE];
__device__ int   g_is64;   // 1 if edge_index delivered as raw int64, 0 if int32

__device__ __forceinline__ float silu_f(float x) {
    return x * (1.0f / (1.0f + __expf(-x)));
}

__device__ __forceinline__ float warp_reduce_add(float v) {
#pragma unroll
    for (int o = 16; o > 0; o >>= 1) v += __shfl_xor_sync(0xffffffffu, v, o);
    return v;
}

__device__ __forceinline__ int load_idx(const int* __restrict__ ei, int pos, int is64) {
    // int32 layout: ei[pos]. int64 LE layout: low word at ei[2*pos].
    return is64 ? ei[2 * pos] : ei[pos];
}

// Fused 2-layer MLP core on a 64-row tile. 256 threads.
template <int KIN>
__device__ __forceinline__ void mlp_core(
    float* __restrict__ As, float* __restrict__ A2, float* __restrict__ Bs,
    float* __restrict__ Ys,
    const float* __restrict__ w1, const float* __restrict__ b1,
    const float* __restrict__ w2, const float* __restrict__ b2)
{
    const int tid = threadIdx.x;
    const int tx = tid & 15;
    const int ty = tid >> 4;

    float4* Bs4 = (float4*)Bs;

    // ---------------- GEMM1: [TM,KIN] @ [KIN,256] ----------------
    float acc[4][16];
#pragma unroll
    for (int i = 0; i < 4; i++)
#pragma unroll
        for (int j = 0; j < 16; j++) acc[i][j] = 0.0f;

    for (int kk = 0; kk < KIN; kk += 16) {
        const float4* wg = (const float4*)(w1 + kk * HN);
#pragma unroll
        for (int t = 0; t < 4; t++) Bs4[tid + t * 256] = wg[tid + t * 256];
        __syncthreads();

#pragma unroll
        for (int k = 0; k < 16; k++) {
            float a[4];
#pragma unroll
            for (int i = 0; i < 4; i++)
                a[i] = As[(ty * 4 + i) * KIN + kk + k];   // broadcast LDS
#pragma unroll
            for (int g = 0; g < 4; g++) {
                float4 b = Bs4[k * 64 + g * 16 + tx];     // conflict-free LDS.128
#pragma unroll
                for (int i = 0; i < 4; i++) {
                    acc[i][g * 4 + 0] = fmaf(a[i], b.x, acc[i][g * 4 + 0]);
                    acc[i][g * 4 + 1] = fmaf(a[i], b.y, acc[i][g * 4 + 1]);
                    acc[i][g * 4 + 2] = fmaf(a[i], b.z, acc[i][g * 4 + 2]);
                    acc[i][g * 4 + 3] = fmaf(a[i], b.w, acc[i][g * 4 + 3]);
                }
            }
        }
        __syncthreads();
    }

    // bias + SiLU -> A2 (hidden tile)
#pragma unroll
    for (int i = 0; i < 4; i++) {
        int r = ty * 4 + i;
#pragma unroll
        for (int g = 0; g < 4; g++) {
            float4 bv = ((const float4*)b1)[g * 16 + tx];
            float4 h;
            h.x = silu_f(acc[i][g * 4 + 0] + bv.x);
            h.y = silu_f(acc[i][g * 4 + 1] + bv.y);
            h.z = silu_f(acc[i][g * 4 + 2] + bv.z);
            h.w = silu_f(acc[i][g * 4 + 3] + bv.w);
            ((float4*)(A2 + r * A2S))[g * 16 + tx] = h;
        }
    }
    __syncthreads();

    // ---------------- GEMM2: [TM,256] @ [256,128] ----------------
    float acc2[4][8];
#pragma unroll
    for (int i = 0; i < 4; i++)
#pragma unroll
        for (int j = 0; j < 8; j++) acc2[i][j] = 0.0f;

    for (int kk = 0; kk < HN; kk += 16) {
        const float4* wg = (const float4*)(w2 + kk * DN);
#pragma unroll
        for (int t = 0; t < 2; t++) Bs4[tid + t * 256] = wg[tid + t * 256];
        __syncthreads();

#pragma unroll
        for (int k = 0; k < 16; k++) {
            float a[4];
#pragma unroll
            for (int i = 0; i < 4; i++)
                a[i] = A2[(ty * 4 + i) * A2S + kk + k];
#pragma unroll
            for (int g = 0; g < 2; g++) {
                float4 b = Bs4[k * 32 + g * 16 + tx];
#pragma unroll
                for (int i = 0; i < 4; i++) {
                    acc2[i][g * 4 + 0] = fmaf(a[i], b.x, acc2[i][g * 4 + 0]);
                    acc2[i][g * 4 + 1] = fmaf(a[i], b.y, acc2[i][g * 4 + 1]);
                    acc2[i][g * 4 + 2] = fmaf(a[i], b.z, acc2[i][g * 4 + 2]);
                    acc2[i][g * 4 + 3] = fmaf(a[i], b.w, acc2[i][g * 4 + 3]);
                }
            }
        }
        __syncthreads();
    }

    // bias -> Ys (pre-LN)
#pragma unroll
    for (int i = 0; i < 4; i++) {
        int r = ty * 4 + i;
#pragma unroll
        for (int g = 0; g < 2; g++) {
            float4 bv = ((const float4*)b2)[g * 16 + tx];
            float4 y;
            y.x = acc2[i][g * 4 + 0] + bv.x;
            y.y = acc2[i][g * 4 + 1] + bv.y;
            y.z = acc2[i][g * 4 + 2] + bv.z;
            y.w = acc2[i][g * 4 + 3] + bv.w;
            ((float4*)(Ys + r * YSS))[g * 16 + tx] = y;
        }
    }
    __syncthreads();
}

// LayerNorm on one row; lane holds cols lane*4..lane*4+3.
__device__ __forceinline__ float4 ln_row(const float* Ys, int rr, int lane,
                                         float4 gm, float4 bt)
{
    float4 v = ((const float4*)(Ys + rr * YSS))[lane];
    float s1 = v.x + v.y + v.z + v.w;
    float s2 = v.x * v.x + v.y * v.y + v.z * v.z + v.w * v.w;
    s1 = warp_reduce_add(s1);
    s2 = warp_reduce_add(s2);
    float mean = s1 * (1.0f / 128.0f);
    float var  = s2 * (1.0f / 128.0f) - mean * mean;
    float rstd = rsqrtf(var + 1e-5f);
    float4 p;
    p.x = (v.x - mean) * rstd * gm.x + bt.x;
    p.y = (v.y - mean) * rstd * gm.y + bt.y;
    p.z = (v.z - mean) * rstd * gm.z + bt.z;
    p.w = (v.w - mean) * rstd * gm.w + bt.w;
    return p;
}

// ------------------------- kernels -------------------------

__global__ void detect_idx_kernel(const int* __restrict__ ei)
{
    // If edge_index is raw int64 (little-endian, values < 2^31), the odd
    // 32-bit words of the first 2048 entries are all zero. With int32 data
    // those positions hold random indices in [0, 40000) — effectively never
    // all zero across 2048 samples.
    __shared__ int any;
    if (threadIdx.x == 0) any = 0;
    __syncthreads();
    for (int i = threadIdx.x; i < 2048; i += blockDim.x)
        if (ei[2 * i + 1] != 0) any = 1;
    __syncthreads();
    if (threadIdx.x == 0) g_is64 = (any == 0) ? 1 : 0;
}

__global__ void zero_scratch_kernel()
{
    int i = blockIdx.x * blockDim.x + threadIdx.x;
    int stride = gridDim.x * blockDim.x;
    for (int j = i; j < NNODE * DN; j += stride) g_agg[j] = 0.0f;
    for (int j = i; j < NNODE; j += stride) g_cnt[j] = 0.0f;
}

__global__ void __launch_bounds__(256, 1)
edge_kernel(const float* __restrict__ sx, const float* __restrict__ rx,
            const float* __restrict__ ea, const int* __restrict__ ei,
            const float* __restrict__ w1, const float* __restrict__ b1,
            const float* __restrict__ w2, const float* __restrict__ b2,
            const float* __restrict__ gam, const float* __restrict__ bet,
            float* __restrict__ edge_out)
{
    extern __shared__ float smem[];
    float* As = smem;                    // TM * 384
    float* A2 = As + TM * 384;           // TM * A2S
    float* Bs = A2 + TM * A2S;           // 4096
    float* Ys = As;                      // alias (As dead before Ys written)

    const int tid = threadIdx.x, lane = tid & 31, warp = tid >> 5;
    const int base = blockIdx.x * TM;
    const int is64 = g_is64;

    // gather: edge_in = [sender_x[src] | receiver_x[dst] | edge_attr]
#pragma unroll
    for (int it = 0; it < 8; it++) {
        int el = warp * 8 + it;
        int e = base + el;
        int s = load_idx(ei, e, is64);
        int d = load_idx(ei, NEDGE + e, is64);
        ((float4*)(As + el * 384))[lane]       = ((const float4*)(sx + (size_t)s * DN))[lane];
        ((float4*)(As + el * 384 + 128))[lane] = ((const float4*)(rx + (size_t)d * DN))[lane];
        ((float4*)(As + el * 384 + 256))[lane] = ((const float4*)(ea + (size_t)e * DN))[lane];
    }
    __syncthreads();

    mlp_core<384>(As, A2, Bs, Ys, w1, b1, w2, b2);

    float4 gm = ((const float4*)gam)[lane];
    float4 bt = ((const float4*)bet)[lane];
#pragma unroll 1
    for (int it = 0; it < 8; it++) {
        int rr = warp * 8 + it;
        int e = base + rr;
        float4 p = ln_row(Ys, rr, lane, gm, bt);
        int d = load_idx(ei, NEDGE + e, is64);
        float4 ev = ((const float4*)(ea + (size_t)e * DN))[lane];
        float4 o;
        o.x = ev.x + p.x; o.y = ev.y + p.y; o.z = ev.z + p.z; o.w = ev.w + p.w;
        ((float4*)(edge_out + (size_t)e * DN))[lane] = o;
        float* ag = g_agg + (size_t)d * DN + lane * 4;
        atomicAdd(ag + 0, p.x);
        atomicAdd(ag + 1, p.y);
        atomicAdd(ag + 2, p.z);
        atomicAdd(ag + 3, p.w);
        if (lane == 0) atomicAdd(&g_cnt[d], 1.0f);
    }
}

__global__ void __launch_bounds__(256, 1)
node_kernel(const float* __restrict__ rx,
            const float* __restrict__ w1, const float* __restrict__ b1,
            const float* __restrict__ w2, const float* __restrict__ b2,
            const float* __restrict__ gam, const float* __restrict__ bet,
            float* __restrict__ recv_out)
{
    extern __shared__ float smem[];
    float* As = smem;                    // TM * 256
    float* A2 = As + TM * 256;
    float* Bs = A2 + TM * A2S;
    float* Ys = As;

    const int tid = threadIdx.x, lane = tid & 31, warp = tid >> 5;
    const int base = blockIdx.x * TM;

#pragma unroll
    for (int it = 0; it < 8; it++) {
        int nl = warp * 8 + it;
        int n = base + nl;
        ((float4*)(As + nl * 256))[lane] = ((const float4*)(rx + (size_t)n * DN))[lane];
        float c = g_cnt[n];
        float inv = 1.0f / fmaxf(c, 1.0f);
        float4 a = ((const float4*)(g_agg + (size_t)n * DN))[lane];
        a.x *= inv; a.y *= inv; a.z *= inv; a.w *= inv;
        ((float4*)(As + nl * 256 + 128))[lane] = a;
    }
    __syncthreads();

    mlp_core<256>(As, A2, Bs, Ys, w1, b1, w2, b2);

    float4 gm = ((const float4*)gam)[lane];
    float4 bt = ((const float4*)bet)[lane];
#pragma unroll 1
    for (int it = 0; it < 8; it++) {
        int rr = warp * 8 + it;
        int n = base + rr;
        float4 p = ln_row(Ys, rr, lane, gm, bt);
        float4 xv = ((const float4*)(rx + (size_t)n * DN))[lane];
        float4 o;
        o.x = xv.x + p.x; o.y = xv.y + p.y; o.z = xv.z + p.z; o.w = xv.w + p.w;
        ((float4*)(recv_out + (size_t)n * DN))[lane] = o;
    }
}

__global__ void __launch_bounds__(256, 1)
sender_kernel(const float* __restrict__ sx,
              const float* __restrict__ w1, const float* __restrict__ b1,
              const float* __restrict__ w2, const float* __restrict__ b2,
              const float* __restrict__ gam, const float* __restrict__ bet,
              float* __restrict__ send_out)
{
    extern __shared__ float smem[];
    float* As = smem;                    // TM*128 input; Ys alias needs TM*YSS
    float* A2 = smem + TM * YSS;
    float* Bs = A2 + TM * A2S;
    float* Ys = As;

    const int tid = threadIdx.x, lane = tid & 31, warp = tid >> 5;
    const int base = blockIdx.x * TM;

#pragma unroll
    for (int it = 0; it < 8; it++) {
        int nl = warp * 8 + it;
        int n = base + nl;
        ((float4*)(As + nl * 128))[lane] = ((const float4*)(sx + (size_t)n * DN))[lane];
    }
    __syncthreads();

    mlp_core<128>(As, A2, Bs, Ys, w1, b1, w2, b2);

    float4 gm = ((const float4*)gam)[lane];
    float4 bt = ((const float4*)bet)[lane];
#pragma unroll 1
    for (int it = 0; it < 8; it++) {
        int rr = warp * 8 + it;
        int n = base + rr;
        float4 p = ln_row(Ys, rr, lane, gm, bt);
        float4 xv = ((const float4*)(sx + (size_t)n * DN))[lane];
        float4 o;
        o.x = xv.x + p.x; o.y = xv.y + p.y; o.z = xv.z + p.z; o.w = xv.w + p.w;
        ((float4*)(send_out + (size_t)n * DN))[lane] = o;
    }
}

// ------------------------- launch -------------------------

extern "C" void kernel_launch(void* const* d_in, const int* in_sizes, int n_in,
                              void* d_out, int out_size)
{
    const float* sx    = (const float*)d_in[0];
    const float* rx    = (const float*)d_in[1];
    const float* ea    = (const float*)d_in[2];
    const int*   ei    = (const int*)d_in[3];
    const float* ew1   = (const float*)d_in[4];
    const float* eb1   = (const float*)d_in[5];
    const float* ew2   = (const float*)d_in[6];
    const float* eb2   = (const float*)d_in[7];
    const float* eg    = (const float*)d_in[8];
    const float* ebeta = (const float*)d_in[9];
    const float* nw1   = (const float*)d_in[10];
    const float* nb1   = (const float*)d_in[11];
    const float* nw2   = (const float*)d_in[12];
    const float* nb2   = (const float*)d_in[13];
    const float* ng    = (const float*)d_in[14];
    const float* nbeta = (const float*)d_in[15];
    const float* sw1   = (const float*)d_in[16];
    const float* sb1   = (const float*)d_in[17];
    const float* sw2   = (const float*)d_in[18];
    const float* sb2   = (const float*)d_in[19];
    const float* sg    = (const float*)d_in[20];
    const float* sbeta = (const float*)d_in[21];

    float* out = (float*)d_out;
    float* send_out = out;                                  // [N, D]
    float* recv_out = out + (size_t)NNODE * DN;             // [N, D]
    float* edge_out = out + (size_t)2 * NNODE * DN;         // [E, D]

    const int smemE = (TM * 384 + TM * A2S + 16 * HN) * (int)sizeof(float);
    const int smemN = (TM * 256 + TM * A2S + 16 * HN) * (int)sizeof(float);
    const int smemS = (TM * YSS + TM * A2S + 16 * HN) * (int)sizeof(float);
    cudaFuncSetAttribute(edge_kernel,   cudaFuncAttributeMaxDynamicSharedMemorySize, smemE);
    cudaFuncSetAttribute(node_kernel,   cudaFuncAttributeMaxDynamicSharedMemorySize, smemN);
    cudaFuncSetAttribute(sender_kernel, cudaFuncAttributeMaxDynamicSharedMemorySize, smemS);

    detect_idx_kernel<<<1, 256>>>(ei);
    zero_scratch_kernel<<<296, 256>>>();

    edge_kernel<<<NEDGE / TM, 256, smemE>>>(
        sx, rx, ea, ei, ew1, eb1, ew2, eb2, eg, ebeta, edge_out);

    sender_kernel<<<NNODE / TM, 256, smemS>>>(
        sx, sw1, sb1, sw2, sb2, sg, sbeta, send_out);

    node_kernel<<<NNODE / TM, 256, smemN>>>(
        rx, nw1, nb1, nw2, nb2, ng, nbeta, recv_out);
}

// round 3
// speedup vs baseline: 1.3194x; 1.3194x over previous
#include <cuda_runtime.h>
#include <math.h>

// Problem constants (fixed per reference)
#define DN     128      // feature dim
#define HN     256      // hidden dim
#define NNODE  40000
#define NEDGE  640000
#define TM     64       // row tile
#define A2S    260      // A2 smem row stride (floats)
#define YSS    132      // Ys smem row stride (floats)
#define KC     32       // k-chunk (weight staging depth)

typedef unsigned long long u64;

// Scratch (device globals: no allocation allowed)
__device__ float g_agg[NNODE * DN];
__device__ float g_cnt[NNODE];
__device__ int   g_is64;   // 1 if edge_index delivered as raw int64, 0 if int32

__device__ __forceinline__ float silu_f(float x) {
    return x * (1.0f / (1.0f + __expf(-x)));
}

__device__ __forceinline__ float warp_reduce_add(float v) {
#pragma unroll
    for (int o = 16; o > 0; o >>= 1) v += __shfl_xor_sync(0xffffffffu, v, o);
    return v;
}

__device__ __forceinline__ int load_idx(const int* __restrict__ ei, int pos, int is64) {
    return is64 ? ei[2 * pos] : ei[pos];
}

// ---- packed fp32x2 helpers (sm_103a FFMA2 path) ----
__device__ __forceinline__ void ffma2(u64& d, u64 a, u64 b) {
    asm("fma.rn.f32x2 %0, %1, %2, %0;" : "+l"(d) : "l"(a), "l"(b));
}
__device__ __forceinline__ u64 pack_dup(float a) {
    u64 r; asm("mov.b64 %0, {%1, %1};" : "=l"(r) : "f"(a)); return r;
}
__device__ __forceinline__ float2 unpack2(u64 v) {
    float2 r; asm("mov.b64 {%0, %1}, %2;" : "=f"(r.x), "=f"(r.y) : "l"(v)); return r;
}

// Fused 2-layer MLP core on a 64-row tile. 256 threads.
// tx = tid&15 (4 output cols each), ty = tid>>4 (4 rows each).
template <int KIN>
__device__ __forceinline__ void mlp_core(
    float* __restrict__ As, float* __restrict__ A2, float* __restrict__ Bs,
    float* __restrict__ Ys,
    const float* __restrict__ w1, const float* __restrict__ b1,
    const float* __restrict__ w2, const float* __restrict__ b2)
{
    const int tid = threadIdx.x;
    const int tx = tid & 15;
    const int ty = tid >> 4;

    float4* Bs4 = (float4*)Bs;
    const ulonglong2* Bsp = (const ulonglong2*)Bs;

    // ---------------- GEMM1: [TM,KIN] @ [KIN,256] ----------------
    u64 acc[4][8];   // 4 rows x 16 cols (8 packed pairs)
#pragma unroll
    for (int i = 0; i < 4; i++)
#pragma unroll
        for (int j = 0; j < 8; j++) acc[i][j] = 0ull;

    for (int kk = 0; kk < KIN; kk += KC) {
        // stage KC x 256 weight chunk (8192 floats)
        const float4* wg = (const float4*)(w1 + kk * HN);
#pragma unroll
        for (int t = 0; t < 8; t++) Bs4[tid + t * 256] = wg[tid + t * 256];
        __syncthreads();

#pragma unroll 8
        for (int k = 0; k < KC; k++) {
            u64 a2[4];
#pragma unroll
            for (int i = 0; i < 4; i++)
                a2[i] = pack_dup(As[(ty * 4 + i) * KIN + kk + k]);
#pragma unroll
            for (int g = 0; g < 4; g++) {
                ulonglong2 b = Bsp[k * 64 + g * 16 + tx];   // 16B conflict-free
#pragma unroll
                for (int i = 0; i < 4; i++) {
                    ffma2(acc[i][g * 2 + 0], a2[i], b.x);
                    ffma2(acc[i][g * 2 + 1], a2[i], b.y);
                }
            }
        }
        __syncthreads();
    }

    // bias + SiLU -> A2 (hidden tile)
#pragma unroll
    for (int i = 0; i < 4; i++) {
        int r = ty * 4 + i;
#pragma unroll
        for (int g = 0; g < 4; g++) {
            float4 bv = ((const float4*)b1)[g * 16 + tx];
            float2 p0 = unpack2(acc[i][g * 2 + 0]);
            float2 p1 = unpack2(acc[i][g * 2 + 1]);
            float4 h;
            h.x = silu_f(p0.x + bv.x);
            h.y = silu_f(p0.y + bv.y);
            h.z = silu_f(p1.x + bv.z);
            h.w = silu_f(p1.y + bv.w);
            ((float4*)(A2 + r * A2S))[g * 16 + tx] = h;
        }
    }
    __syncthreads();

    // ---------------- GEMM2: [TM,256] @ [256,128] ----------------
    u64 acc2[4][4];  // 4 rows x 8 cols (4 packed pairs)
#pragma unroll
    for (int i = 0; i < 4; i++)
#pragma unroll
        for (int j = 0; j < 4; j++) acc2[i][j] = 0ull;

    for (int kk = 0; kk < HN; kk += KC) {
        const float4* wg = (const float4*)(w2 + kk * DN);
#pragma unroll
        for (int t = 0; t < 4; t++) Bs4[tid + t * 256] = wg[tid + t * 256];
        __syncthreads();

#pragma unroll 8
        for (int k = 0; k < KC; k++) {
            u64 a2[4];
#pragma unroll
            for (int i = 0; i < 4; i++)
                a2[i] = pack_dup(A2[(ty * 4 + i) * A2S + kk + k]);
#pragma unroll
            for (int g = 0; g < 2; g++) {
                ulonglong2 b = Bsp[k * 32 + g * 16 + tx];
#pragma unroll
                for (int i = 0; i < 4; i++) {
                    ffma2(acc2[i][g * 2 + 0], a2[i], b.x);
                    ffma2(acc2[i][g * 2 + 1], a2[i], b.y);
                }
            }
        }
        __syncthreads();
    }

    // bias -> Ys (pre-LN)
#pragma unroll
    for (int i = 0; i < 4; i++) {
        int r = ty * 4 + i;
#pragma unroll
        for (int g = 0; g < 2; g++) {
            float4 bv = ((const float4*)b2)[g * 16 + tx];
            float2 p0 = unpack2(acc2[i][g * 2 + 0]);
            float2 p1 = unpack2(acc2[i][g * 2 + 1]);
            float4 y;
            y.x = p0.x + bv.x;
            y.y = p0.y + bv.y;
            y.z = p1.x + bv.z;
            y.w = p1.y + bv.w;
            ((float4*)(Ys + r * YSS))[g * 16 + tx] = y;
        }
    }
    __syncthreads();
}

// LayerNorm on one row; lane holds cols lane*4..lane*4+3.
__device__ __forceinline__ float4 ln_row(const float* Ys, int rr, int lane,
                                         float4 gm, float4 bt)
{
    float4 v = ((const float4*)(Ys + rr * YSS))[lane];
    float s1 = v.x + v.y + v.z + v.w;
    float s2 = v.x * v.x + v.y * v.y + v.z * v.z + v.w * v.w;
    s1 = warp_reduce_add(s1);
    s2 = warp_reduce_add(s2);
    float mean = s1 * (1.0f / 128.0f);
    float var  = s2 * (1.0f / 128.0f) - mean * mean;
    float rstd = rsqrtf(var + 1e-5f);
    float4 p;
    p.x = (v.x - mean) * rstd * gm.x + bt.x;
    p.y = (v.y - mean) * rstd * gm.y + bt.y;
    p.z = (v.z - mean) * rstd * gm.z + bt.z;
    p.w = (v.w - mean) * rstd * gm.w + bt.w;
    return p;
}

// ------------------------- kernels -------------------------

__global__ void detect_idx_kernel(const int* __restrict__ ei)
{
    __shared__ int any;
    if (threadIdx.x == 0) any = 0;
    __syncthreads();
    for (int i = threadIdx.x; i < 2048; i += blockDim.x)
        if (ei[2 * i + 1] != 0) any = 1;
    __syncthreads();
    if (threadIdx.x == 0) g_is64 = (any == 0) ? 1 : 0;
}

__global__ void zero_scratch_kernel()
{
    int i = blockIdx.x * blockDim.x + threadIdx.x;
    int stride = gridDim.x * blockDim.x;
    for (int j = i; j < NNODE * DN; j += stride) g_agg[j] = 0.0f;
    for (int j = i; j < NNODE; j += stride) g_cnt[j] = 0.0f;
}

__global__ void __launch_bounds__(256, 1)
edge_kernel(const float* __restrict__ sx, const float* __restrict__ rx,
            const float* __restrict__ ea, const int* __restrict__ ei,
            const float* __restrict__ w1, const float* __restrict__ b1,
            const float* __restrict__ w2, const float* __restrict__ b2,
            const float* __restrict__ gam, const float* __restrict__ bet,
            float* __restrict__ edge_out)
{
    extern __shared__ float smem[];
    float* As = smem;                    // TM * 384
    float* A2 = As + TM * 384;           // TM * A2S
    float* Bs = A2 + TM * A2S;           // KC * 256
    float* Ys = As;                      // alias (As dead before Ys written)

    const int tid = threadIdx.x, lane = tid & 31, warp = tid >> 5;
    const int base = blockIdx.x * TM;
    const int is64 = g_is64;

    // gather: edge_in = [sender_x[src] | receiver_x[dst] | edge_attr]
#pragma unroll
    for (int it = 0; it < 8; it++) {
        int el = warp * 8 + it;
        int e = base + el;
        int s = load_idx(ei, e, is64);
        int d = load_idx(ei, NEDGE + e, is64);
        ((float4*)(As + el * 384))[lane]       = ((const float4*)(sx + (size_t)s * DN))[lane];
        ((float4*)(As + el * 384 + 128))[lane] = ((const float4*)(rx + (size_t)d * DN))[lane];
        ((float4*)(As + el * 384 + 256))[lane] = ((const float4*)(ea + (size_t)e * DN))[lane];
    }
    __syncthreads();

    mlp_core<384>(As, A2, Bs, Ys, w1, b1, w2, b2);

    float4 gm = ((const float4*)gam)[lane];
    float4 bt = ((const float4*)bet)[lane];
#pragma unroll 1
    for (int it = 0; it < 8; it++) {
        int rr = warp * 8 + it;
        int e = base + rr;
        float4 p = ln_row(Ys, rr, lane, gm, bt);
        int d = load_idx(ei, NEDGE + e, is64);
        float4 ev = ((const float4*)(ea + (size_t)e * DN))[lane];
        float4 o;
        o.x = ev.x + p.x; o.y = ev.y + p.y; o.z = ev.z + p.z; o.w = ev.w + p.w;
        ((float4*)(edge_out + (size_t)e * DN))[lane] = o;
        float* ag = g_agg + (size_t)d * DN + lane * 4;
        atomicAdd(ag + 0, p.x);
        atomicAdd(ag + 1, p.y);
        atomicAdd(ag + 2, p.z);
        atomicAdd(ag + 3, p.w);
        if (lane == 0) atomicAdd(&g_cnt[d], 1.0f);
    }
}

__global__ void __launch_bounds__(256, 1)
node_kernel(const float* __restrict__ rx,
            const float* __restrict__ w1, const float* __restrict__ b1,
            const float* __restrict__ w2, const float* __restrict__ b2,
            const float* __restrict__ gam, const float* __restrict__ bet,
            float* __restrict__ recv_out)
{
    extern __shared__ float smem[];
    float* As = smem;                    // TM * 256
    float* A2 = As + TM * 256;
    float* Bs = A2 + TM * A2S;
    float* Ys = As;

    const int tid = threadIdx.x, lane = tid & 31, warp = tid >> 5;
    const int base = blockIdx.x * TM;

#pragma unroll
    for (int it = 0; it < 8; it++) {
        int nl = warp * 8 + it;
        int n = base + nl;
        ((float4*)(As + nl * 256))[lane] = ((const float4*)(rx + (size_t)n * DN))[lane];
        float c = g_cnt[n];
        float inv = 1.0f / fmaxf(c, 1.0f);
        float4 a = ((const float4*)(g_agg + (size_t)n * DN))[lane];
        a.x *= inv; a.y *= inv; a.z *= inv; a.w *= inv;
        ((float4*)(As + nl * 256 + 128))[lane] = a;
    }
    __syncthreads();

    mlp_core<256>(As, A2, Bs, Ys, w1, b1, w2, b2);

    float4 gm = ((const float4*)gam)[lane];
    float4 bt = ((const float4*)bet)[lane];
#pragma unroll 1
    for (int it = 0; it < 8; it++) {
        int rr = warp * 8 + it;
        int n = base + rr;
        float4 p = ln_row(Ys, rr, lane, gm, bt);
        float4 xv = ((const float4*)(rx + (size_t)n * DN))[lane];
        float4 o;
        o.x = xv.x + p.x; o.y = xv.y + p.y; o.z = xv.z + p.z; o.w = xv.w + p.w;
        ((float4*)(recv_out + (size_t)n * DN))[lane] = o;
    }
}

__global__ void __launch_bounds__(256, 1)
sender_kernel(const float* __restrict__ sx,
              const float* __restrict__ w1, const float* __restrict__ b1,
              const float* __restrict__ w2, const float* __restrict__ b2,
              const float* __restrict__ gam, const float* __restrict__ bet,
              float* __restrict__ send_out)
{
    extern __shared__ float smem[];
    float* As = smem;                    // TM*128 input; Ys alias needs TM*YSS
    float* A2 = smem + TM * YSS;
    float* Bs = A2 + TM * A2S;
    float* Ys = As;

    const int tid = threadIdx.x, lane = tid & 31, warp = tid >> 5;
    const int base = blockIdx.x * TM;

#pragma unroll
    for (int it = 0; it < 8; it++) {
        int nl = warp * 8 + it;
        int n = base + nl;
        ((float4*)(As + nl * 128))[lane] = ((const float4*)(sx + (size_t)n * DN))[lane];
    }
    __syncthreads();

    mlp_core<128>(As, A2, Bs, Ys, w1, b1, w2, b2);

    float4 gm = ((const float4*)gam)[lane];
    float4 bt = ((const float4*)bet)[lane];
#pragma unroll 1
    for (int it = 0; it < 8; it++) {
        int rr = warp * 8 + it;
        int n = base + rr;
        float4 p = ln_row(Ys, rr, lane, gm, bt);
        float4 xv = ((const float4*)(sx + (size_t)n * DN))[lane];
        float4 o;
        o.x = xv.x + p.x; o.y = xv.y + p.y; o.z = xv.z + p.z; o.w = xv.w + p.w;
        ((float4*)(send_out + (size_t)n * DN))[lane] = o;
    }
}

// ------------------------- launch -------------------------

extern "C" void kernel_launch(void* const* d_in, const int* in_sizes, int n_in,
                              void* d_out, int out_size)
{
    const float* sx    = (const float*)d_in[0];
    const float* rx    = (const float*)d_in[1];
    const float* ea    = (const float*)d_in[2];
    const int*   ei    = (const int*)d_in[3];
    const float* ew1   = (const float*)d_in[4];
    const float* eb1   = (const float*)d_in[5];
    const float* ew2   = (const float*)d_in[6];
    const float* eb2   = (const float*)d_in[7];
    const float* eg    = (const float*)d_in[8];
    const float* ebeta = (const float*)d_in[9];
    const float* nw1   = (const float*)d_in[10];
    const float* nb1   = (const float*)d_in[11];
    const float* nw2   = (const float*)d_in[12];
    const float* nb2   = (const float*)d_in[13];
    const float* ng    = (const float*)d_in[14];
    const float* nbeta = (const float*)d_in[15];
    const float* sw1   = (const float*)d_in[16];
    const float* sb1   = (const float*)d_in[17];
    const float* sw2   = (const float*)d_in[18];
    const float* sb2   = (const float*)d_in[19];
    const float* sg    = (const float*)d_in[20];
    const float* sbeta = (const float*)d_in[21];

    float* out = (float*)d_out;
    float* send_out = out;                                  // [N, D]
    float* recv_out = out + (size_t)NNODE * DN;             // [N, D]
    float* edge_out = out + (size_t)2 * NNODE * DN;         // [E, D]

    const int smemE = (TM * 384 + TM * A2S + KC * HN) * (int)sizeof(float);
    const int smemN = (TM * 256 + TM * A2S + KC * HN) * (int)sizeof(float);
    const int smemS = (TM * YSS + TM * A2S + KC * HN) * (int)sizeof(float);
    cudaFuncSetAttribute(edge_kernel,   cudaFuncAttributeMaxDynamicSharedMemorySize, smemE);
    cudaFuncSetAttribute(node_kernel,   cudaFuncAttributeMaxDynamicSharedMemorySize, smemN);
    cudaFuncSetAttribute(sender_kernel, cudaFuncAttributeMaxDynamicSharedMemorySize, smemS);

    detect_idx_kernel<<<1, 256>>>(ei);
    zero_scratch_kernel<<<296, 256>>>();

    edge_kernel<<<NEDGE / TM, 256, smemE>>>(
        sx, rx, ea, ei, ew1, eb1, ew2, eb2, eg, ebeta, edge_out);

    sender_kernel<<<NNODE / TM, 256, smemS>>>(
        sx, sw1, sb1, sw2, sb2, sg, sbeta, send_out);

    node_kernel<<<NNODE / TM, 256, smemN>>>(
        rx, nw1, nb1, nw2, nb2, ng, nbeta, recv_out);
}